// round 2
// baseline (speedup 1.0000x reference)
#include <cuda_runtime.h>
#include <math.h>

#define BSZ 8
#define H   512
#define P   128
#define LSEQ 8192

// Scratch (allocation-free rule: __device__ globals).
// Bu / xs stored as interleaved complex float2, packed in float4 for vector I/O.
__device__ float4 g_Bu4[(size_t)BSZ * P * LSEQ / 2];   // 67 MB
__device__ float2 g_Bbar[P * H];                       // B_bar (complex), p-major
__device__ float2 g_Lbar[P];                           // Lambda_bar (complex)
__device__ float  g_A2[H * 2 * P];                     // [h][2p]=2*C_re, [h][2p+1]=-2*C_im

__device__ __forceinline__ float2 cmul(float2 a, float2 b) {
    return make_float2(a.x * b.x - a.y * b.y, a.x * b.y + a.y * b.x);
}

// ---------------------------------------------------------------------------
// Setup: Lambda_bar, B_bar (fp64 internally), folded C matrix.
// ---------------------------------------------------------------------------
__global__ void setup_kernel(const float* __restrict__ Lre, const float* __restrict__ Lim,
                             const float* __restrict__ Bm, const float* __restrict__ Cm,
                             const float* __restrict__ logstep) {
    int tid = blockIdx.x * blockDim.x + threadIdx.x;
    int stride = gridDim.x * blockDim.x;

    if (tid < P) {
        double st = exp((double)logstep[tid]);
        double zre = (double)Lre[tid] * st, zim = (double)Lim[tid] * st;
        double er = exp(zre);
        g_Lbar[tid] = make_float2((float)(er * cos(zim)), (float)(er * sin(zim)));
    }

    for (int i = tid; i < P * H; i += stride) {
        int p = i >> 9;                 // H = 512
        double st  = exp((double)logstep[p]);
        double lre = (double)Lre[p], lim = (double)Lim[p];
        double zre = lre * st, zim = lim * st;
        double er  = exp(zre);
        double numr = er * cos(zim) - 1.0;   // Lambda_bar - 1
        double numi = er * sin(zim);
        double den  = lre * lre + lim * lim;
        double gre = (numr * lre + numi * lim) / den;   // (Lbar-1)/Lambda
        double gim = (numi * lre - numr * lim) / den;
        float br = Bm[2 * i], bi = Bm[2 * i + 1];
        g_Bbar[i] = make_float2((float)(gre * (double)br - gim * (double)bi),
                                (float)(gre * (double)bi + gim * (double)br));
    }

    for (int i = tid; i < H * 2 * P; i += stride) {
        int h = i >> 8;                 // 2P = 256
        int k = i & 255;
        int p = k >> 1;
        float cre = Cm[(h * P + p) * 2], cim = Cm[(h * P + p) * 2 + 1];
        g_A2[i] = (k & 1) ? -2.0f * cim : 2.0f * cre;
    }
}

// ---------------------------------------------------------------------------
// K1: Bu[b,p,l] = sum_h B_bar[p,h] * u[b,h,l]   (complex out, real u)
// Tile: BM=128 (all P), BN=64 (L), BK=16 (H). 256 threads, 8x4 micro-tile,
// two fp32 accumulators (re/im) per element.
// ---------------------------------------------------------------------------
__global__ void __launch_bounds__(256) bu_gemm_kernel(const float* __restrict__ u) {
    const int b   = blockIdx.z;
    const int n0  = blockIdx.x * 64;
    const int row = threadIdx.x >> 4;   // 0..15  -> 8 p each
    const int col = threadIdx.x & 15;   // 0..15  -> 4 l each

    __shared__ __align__(16) float As_re[16][132];
    __shared__ __align__(16) float As_im[16][132];
    __shared__ __align__(16) float Us[16][64];

    float2 acc[8][4];
#pragma unroll
    for (int m = 0; m < 8; m++)
#pragma unroll
        for (int n = 0; n < 4; n++) acc[m][n] = make_float2(0.f, 0.f);

    const float* ub = u + (size_t)b * H * LSEQ;

    for (int k0 = 0; k0 < H; k0 += 16) {
#pragma unroll
        for (int i = 0; i < 8; i++) {
            int idx = threadIdx.x + i * 256;
            int p = idx >> 4, kk = idx & 15;
            float2 v = g_Bbar[p * H + k0 + kk];
            As_re[kk][p] = v.x;
            As_im[kk][p] = v.y;
        }
#pragma unroll
        for (int i = 0; i < 4; i++) {
            int idx = threadIdx.x + i * 256;
            int hh = idx >> 6, l = idx & 63;
            Us[hh][l] = ub[(size_t)(k0 + hh) * LSEQ + n0 + l];
        }
        __syncthreads();

#pragma unroll
        for (int kk = 0; kk < 16; kk++) {
            float4 ar0 = *(const float4*)&As_re[kk][row * 8];
            float4 ar1 = *(const float4*)&As_re[kk][row * 8 + 4];
            float4 ai0 = *(const float4*)&As_im[kk][row * 8];
            float4 ai1 = *(const float4*)&As_im[kk][row * 8 + 4];
            float4 uu  = *(const float4*)&Us[kk][col * 4];
            float ar[8] = {ar0.x, ar0.y, ar0.z, ar0.w, ar1.x, ar1.y, ar1.z, ar1.w};
            float ai[8] = {ai0.x, ai0.y, ai0.z, ai0.w, ai1.x, ai1.y, ai1.z, ai1.w};
            float un[4] = {uu.x, uu.y, uu.z, uu.w};
#pragma unroll
            for (int m = 0; m < 8; m++)
#pragma unroll
                for (int n = 0; n < 4; n++) {
                    acc[m][n].x += ar[m] * un[n];
                    acc[m][n].y += ai[m] * un[n];
                }
        }
        __syncthreads();
    }

#pragma unroll
    for (int m = 0; m < 8; m++) {
        int p = row * 8 + m;
        size_t base = ((size_t)(b * P + p) * LSEQ + n0 + col * 4) >> 1;
        g_Bu4[base]     = make_float4(acc[m][0].x, acc[m][0].y, acc[m][1].x, acc[m][1].y);
        g_Bu4[base + 1] = make_float4(acc[m][2].x, acc[m][2].y, acc[m][3].x, acc[m][3].y);
    }
}

// ---------------------------------------------------------------------------
// K2: in-place scan along L for each (b,p): x_l = a*x_{l-1} + Bu_l.
// One block per sequence; 512 threads x 16 elems; Kogge-Stone over thread
// aggregates with multiplier a^(16d) obtained by repeated squaring.
// ---------------------------------------------------------------------------
__global__ void __launch_bounds__(512) scan_kernel() {
    const int seq = blockIdx.x;          // b*P + p
    const int p   = seq & (P - 1);
    const float2 a = g_Lbar[p];
    const int t = threadIdx.x;

    float2* base = (float2*)g_Bu4 + (size_t)seq * LSEQ;
    float4* b4   = (float4*)(base + t * 16);

    float2 x[16];
#pragma unroll
    for (int i = 0; i < 8; i++) {
        float4 v = b4[i];
        x[2 * i]     = make_float2(v.x, v.y);
        x[2 * i + 1] = make_float2(v.z, v.w);
    }

    float2 v = make_float2(0.f, 0.f);
#pragma unroll
    for (int j = 0; j < 16; j++) {
        float2 av = cmul(a, v);
        v = make_float2(av.x + x[j].x, av.y + x[j].y);
        x[j] = v;                        // local inclusive scan
    }

    __shared__ float2 s[512];
    s[t] = v;
    float2 f = cmul(a, a);               // a^2
    f = cmul(f, f);                      // a^4
    f = cmul(f, f);                      // a^8
    f = cmul(f, f);                      // a^16
    __syncthreads();

    for (int d = 1; d < 512; d <<= 1) {
        float2 prev = (t >= d) ? s[t - d] : make_float2(0.f, 0.f);
        __syncthreads();
        if (t >= d) {
            float2 cur = s[t];
            float2 add = cmul(f, prev);
            s[t] = make_float2(cur.x + add.x, cur.y + add.y);
        }
        __syncthreads();
        f = cmul(f, f);
    }

    float2 carry = (t > 0) ? s[t - 1] : make_float2(0.f, 0.f);
    float2 pw = a;
#pragma unroll
    for (int j = 0; j < 16; j++) {
        float2 add = cmul(pw, carry);
        x[j].x += add.x;
        x[j].y += add.y;
        pw = cmul(pw, a);
    }

#pragma unroll
    for (int i = 0; i < 8; i++)
        b4[i] = make_float4(x[2 * i].x, x[2 * i].y, x[2 * i + 1].x, x[2 * i + 1].y);
}

// ---------------------------------------------------------------------------
// K3: ys[b,h,l] = gelu( A2[h,:] . X'[:,l] + D[h]*u[b,h,l] )
// A2 is the 2.0/real-part-folded C matrix, X' = [xs_re; xs_im] interleaved.
// Tile: BM=128 (H), BN=64 (L), BK=16 (2P=256). Epilogue fused.
// ---------------------------------------------------------------------------
__global__ void __launch_bounds__(256) out_gemm_kernel(const float* __restrict__ u,
                                                       const float* __restrict__ D,
                                                       float* __restrict__ out) {
    const int b   = blockIdx.z;
    const int n0  = blockIdx.x * 64;
    const int m0  = blockIdx.y * 128;
    const int row = threadIdx.x >> 4;
    const int col = threadIdx.x & 15;

    __shared__ __align__(16) float As[16][132];
    __shared__ __align__(16) float Bs[16][64];

    float acc[8][4] = {};
    const float2* xs = (const float2*)g_Bu4;

    for (int k0 = 0; k0 < 2 * P; k0 += 16) {
#pragma unroll
        for (int i = 0; i < 8; i++) {
            int idx = threadIdx.x + i * 256;
            int h = idx >> 4, kk = idx & 15;
            As[kk][h] = g_A2[(size_t)(m0 + h) * 256 + k0 + kk];
        }
        {
            int pr0 = k0 >> 1;
#pragma unroll
            for (int i = 0; i < 2; i++) {
                int idx = threadIdx.x + i * 256;
                int pl = idx >> 6, l = idx & 63;
                float2 v = xs[(size_t)(b * P + pr0 + pl) * LSEQ + n0 + l];
                Bs[2 * pl][l]     = v.x;
                Bs[2 * pl + 1][l] = v.y;
            }
        }
        __syncthreads();

#pragma unroll
        for (int kk = 0; kk < 16; kk++) {
            float4 a0 = *(const float4*)&As[kk][row * 8];
            float4 a1 = *(const float4*)&As[kk][row * 8 + 4];
            float4 uu = *(const float4*)&Bs[kk][col * 4];
            float am[8] = {a0.x, a0.y, a0.z, a0.w, a1.x, a1.y, a1.z, a1.w};
            float un[4] = {uu.x, uu.y, uu.z, uu.w};
#pragma unroll
            for (int m = 0; m < 8; m++)
#pragma unroll
                for (int n = 0; n < 4; n++) acc[m][n] += am[m] * un[n];
        }
        __syncthreads();
    }

#pragma unroll
    for (int m = 0; m < 8; m++) {
        int h = m0 + row * 8 + m;
        size_t ubase = (size_t)(b * H + h) * LSEQ + n0 + col * 4;
        float4 uv = *(const float4*)(u + ubase);
        float dd = D[h];
        float vals[4] = {acc[m][0] + dd * uv.x, acc[m][1] + dd * uv.y,
                         acc[m][2] + dd * uv.z, acc[m][3] + dd * uv.w};
#pragma unroll
        for (int n = 0; n < 4; n++) {
            float xv = vals[n];
            vals[n] = 0.5f * xv * (1.0f + erff(xv * 0.70710678118654752f));
        }
        *(float4*)(out + ubase) = make_float4(vals[0], vals[1], vals[2], vals[3]);
    }
}

// ---------------------------------------------------------------------------
extern "C" void kernel_launch(void* const* d_in, const int* in_sizes, int n_in,
                              void* d_out, int out_size) {
    const float* u   = (const float*)d_in[0];   // input_sequence (B,1,H,1,L)
    const float* Lre = (const float*)d_in[1];
    const float* Lim = (const float*)d_in[2];
    const float* Bm  = (const float*)d_in[3];   // (P,H,2)
    const float* Cm  = (const float*)d_in[4];   // (H,P,2)
    const float* D   = (const float*)d_in[5];   // (H,)
    const float* ls  = (const float*)d_in[6];   // (P,1)
    float* out = (float*)d_out;

    setup_kernel<<<256, 256>>>(Lre, Lim, Bm, Cm, ls);

    dim3 g1(LSEQ / 64, 1, BSZ);
    bu_gemm_kernel<<<g1, 256>>>(u);

    scan_kernel<<<BSZ * P, 512>>>();

    dim3 g3(LSEQ / 64, H / 128, BSZ);
    out_gemm_kernel<<<g3, 256>>>(u, D, out);
}